// round 9
// baseline (speedup 1.0000x reference)
#include <cuda_runtime.h>
#include <cstdint>

// Problem shape constants (fixed by setup_inputs)
#define B_ 32
#define M_ 512
#define L_ 128
#define N_ 64
#define T_ 40
#define A_ 6
#define Z_ 64
#define C_ 3

#define WARPS_PER_BLOCK 8   // 40 t's = exactly 5 blocks per (b,n)

static __device__ __constant__ float kEPS = 1e-8f;

// ---------------------------------------------------------------------------
// Fused kernel, barrier-late ordering. One warp per (b,n,t); 8 warps/block;
// each block covers exactly one (b,n) (T=40 = 5 * 8).
//   Phase 1 (all warps): stream decision_features (3x LDG.128), z, ctx, fa;
//                        complete all butterflies. All HBM traffic in flight
//                        BEFORE anyone can block.
//   Phase 2 (warp 0):    frenet projection for this bn -> s_fdot.
//   Phase 3 (all):       __syncthreads, add fdot, subtract masked mean, store.
// The projection's long latency chain overlaps with the other ~5 resident
// blocks' streaming instead of stalling an empty pipeline.
// ---------------------------------------------------------------------------
__global__ __launch_bounds__(32 * WARPS_PER_BLOCK, 6)
void fused_logits_kernel(const float* __restrict__ poly,
                         const int* __restrict__ idx,
                         const float* __restrict__ pts,
                         const float* __restrict__ z,
                         const float* __restrict__ df,
                         const float* __restrict__ ctx,
                         const int* __restrict__ fa,
                         const float* __restrict__ w,
                         const float* __restrict__ bias,
                         float* __restrict__ out) {
    const int lane = threadIdx.x & 31;
    const int warp = threadIdx.x >> 5;
    const int bn   = blockIdx.x / 5;                 // (b*N + n)
    const int t    = (blockIdx.x % 5) * WARPS_PER_BLOCK + warp;
    const int gw   = bn * T_ + t;                    // (b*N+n)*T + t

    __shared__ float s_fdot;   // frenet·u_ctx_w + u_ctx_b for this bn

    const float w0 = __ldg(w), w1 = __ldg(w + 1), w2 = __ldg(w + 2);

    // ================= Phase 1: streaming + reductions (all warps) =========
    const int h = lane >> 4;      // half: 0 -> even actions, 1 -> odd actions
    const int q = lane & 15;

    // z as float4 per lane, replicated across halves
    const float4 z4 = *reinterpret_cast<const float4*>(z + (size_t)bn * Z_ + 4 * q);

    // 3 coalesced 512B loads: pair p covers actions (2p, 2p+1)
    const float* dfb = df + (size_t)gw * (A_ * Z_) + 4 * lane;
    float4 v[3];
#pragma unroll
    for (int p = 0; p < 3; ++p)
        v[p] = *reinterpret_cast<const float4*>(dfb + p * 2 * Z_);

    // ctx: 18 contiguous floats, lanes 0..17 coalesced (issued early)
    const size_t cb = (size_t)gw * (A_ * C_);
    const float cv = (lane < A_ * C_) ? __ldg(ctx + cb + lane) : 0.f;
    // feasibility (issued early)
    const int f = (lane < A_) ? __ldg(fa + (size_t)gw * A_ + lane) : 0;

    float acc[3];
#pragma unroll
    for (int p = 0; p < 3; ++p)
        acc[p] = v[p].x * z4.x + v[p].y * z4.y + v[p].z * z4.z + v[p].w * z4.w;

    // 4-level butterfly within each 16-lane half:
    // afterwards every lane in half h holds the full sum for action 2p+h
#pragma unroll
    for (int p = 0; p < 3; ++p) {
#pragma unroll
        for (int off = 8; off > 0; off >>= 1)
            acc[p] += __shfl_xor_sync(0xffffffffu, acc[p], off);
    }

    // u partial: segmented 3-sum of ctx·w, valid at lanes 3a (a = 0..5)
    const int   c  = lane % 3;
    const float wc = (c == 0) ? w0 : ((c == 1) ? w1 : w2);
    const float pterm = cv * wc;
    const float qs = pterm + __shfl_down_sync(0xffffffffu, pterm, 1)
                           + __shfl_down_sync(0xffffffffu, pterm, 2);
    // lane in half h picks up ctx-part of u for its actions 2r+h (r = 0..2)
    float ua[3];
#pragma unroll
    for (int r = 0; r < 3; ++r)
        ua[r] = __shfl_sync(0xffffffffu, qs, 3 * (2 * r + h));

    const unsigned fm = __ballot_sync(0xffffffffu, (f != 0) && (lane < A_));
    const unsigned em = fm ? fm : 0x3fu;
    const int cnt = __popc(em);

    // masked partial sum of ctx-part within this half (fdot contribution to
    // the mean is handled analytically: mean includes fdot exactly once,
    // so (u - umean) = (ua + fdot) - (ctxmean + fdot) = ua - ctxmean).
    float part = 0.f;
#pragma unroll
    for (int r = 0; r < 3; ++r)
        part += ((em >> (2 * r + h)) & 1u) ? ua[r] : 0.f;
    const float tot = part + __shfl_xor_sync(0xffffffffu, part, 16);
    const float ctxmean = tot / fmaxf((float)cnt, 1e-6f);

    // ================= Phase 2: frenet projection (warp 0 only) ============
    if (warp == 0) {
        const int b   = bn >> 6;                     // N_ = 64
        const int pid = __ldg(idx + bn);
        const float* pl = poly + (((size_t)b * M_ + (size_t)pid) * L_) * 2;
        const float px = __ldg(pts + 2 * bn);
        const float py = __ldg(pts + 2 * bn + 1);

        float segl[4], tcl[4], dd[4], sgnd[4], tanx[4], lpre[4];
        float lsum = 0.f;
#pragma unroll
        for (int k = 0; k < 4; ++k) {
            const int j = 4 * lane + k;
            const bool valid = (j < L_ - 1);
            float2 p0 = make_float2(0.f, 0.f), p1 = make_float2(0.f, 0.f);
            if (valid) {
                p0 = *reinterpret_cast<const float2*>(pl + 2 * j);
                p1 = *reinterpret_cast<const float2*>(pl + 2 * j + 2);
            }
            const float vx = p1.x - p0.x, vy = p1.y - p0.y;
            const float v2 = fmaxf(vx * vx + vy * vy, kEPS);
            const float sl = valid ? sqrtf(v2) : 0.f;
            const float wx = px - p0.x, wy = py - p0.y;
            const float tt = fminf(fmaxf((wx * vx + wy * vy) / v2, 0.f), 1.f);
            const float dx = wx - tt * vx, dy = wy - tt * vy;
            const float qd = dx * dx + dy * dy;
            dd[k] = valid ? qd : 3.0e38f;
            const float cross = vx * dy - vy * dx;
            const float sg = (cross > 0.f) ? 1.f : ((cross < 0.f) ? -1.f : 1.f);
            sgnd[k] = sg * sqrtf(fmaxf(qd, kEPS));
            tanx[k] = vx / fmaxf(sl, kEPS);
            segl[k] = sl;
            tcl[k]  = tt;
            lpre[k] = lsum;
            lsum += sl;
        }
        // exclusive warp prefix sum of per-lane length totals
        float run = lsum;
#pragma unroll
        for (int off = 1; off < 32; off <<= 1) {
            const float vp = __shfl_up_sync(0xffffffffu, run, off);
            if (lane >= off) run += vp;
        }
        const float excl = run - lsum;

        float bd = 3.4e38f, bs = 0.f, bdd = 0.f, bt = 0.f;
        int   bj = 1 << 30;
#pragma unroll
        for (int k = 0; k < 4; ++k) {
            const float s = excl + lpre[k] + tcl[k] * segl[k];
            if (dd[k] < bd) {
                bd = dd[k]; bj = 4 * lane + k; bs = s; bdd = sgnd[k]; bt = tanx[k];
            }
        }
#pragma unroll
        for (int off = 16; off > 0; off >>= 1) {
            const float od  = __shfl_xor_sync(0xffffffffu, bd, off);
            const int   oj  = __shfl_xor_sync(0xffffffffu, bj, off);
            const float os  = __shfl_xor_sync(0xffffffffu, bs, off);
            const float odd = __shfl_xor_sync(0xffffffffu, bdd, off);
            const float ot  = __shfl_xor_sync(0xffffffffu, bt, off);
            if (od < bd || (od == bd && oj < bj)) {
                bd = od; bj = oj; bs = os; bdd = odd; bt = ot;
            }
        }
        if (lane == 0) {
            s_fdot = (bs * (1.f / 50.f)) * w0 + (bdd * (1.f / 3.6f)) * w1
                     + bt * w2 + __ldg(bias);
        }
    }

    // ================= Phase 3: combine + store ============================
    __syncthreads();
    const float fdot = s_fdot;

    // lanes 0 and 16 write even/odd actions respectively.
    // logits = acc + (ua + fdot) - (ctxmean + fdot) ... wait: umean includes
    // fdot once (uniform over actions), so u - umean = ua - ctxmean + 0?
    // No: u = ua + fdot; umean = ctxmean + fdot  =>  u - umean = ua - ctxmean.
    // fdot cancels exactly; it is needed only... it cancels! But the
    // reference computes it the same way (uniform constant added to every
    // action, then mean-subtracted over the feasibility mask — the mask mean
    // of a constant is the constant). Keep the subtraction explicit with
    // fdot for bit-level parity with earlier passing rounds.
    if (q == 0) {
        float* ob = out + (size_t)gw * A_ + h;
#pragma unroll
        for (int r = 0; r < 3; ++r)
            ob[2 * r] = acc[r] + ((ua[r] + fdot) - (ctxmean + fdot));
    }
}

// ---------------------------------------------------------------------------
// kernel_launch: inputs in metadata order:
//   0 map_polylines (B,M,L,2) f32   1 idx (B,N) i32       2 pts (B,N,2) f32
//   3 z (B,N,Z) f32                 4 decision_features (B,N,T,A,Z) f32
//   5 ctx_features (B,N,T,A,C) f32  6 feasible_actions (B,N,T,A) i32
//   7 u_ctx_w (C,) f32              8 u_ctx_b (1,) f32
// output: logits (B,N,T,A) f32
// ---------------------------------------------------------------------------
extern "C" void kernel_launch(void* const* d_in, const int* in_sizes, int n_in,
                              void* d_out, int out_size) {
    const float* poly = (const float*)d_in[0];
    const int*   idx  = (const int*)  d_in[1];
    const float* pts  = (const float*)d_in[2];
    const float* z    = (const float*)d_in[3];
    const float* df   = (const float*)d_in[4];
    const float* ctx  = (const float*)d_in[5];
    const int*   fa   = (const int*)  d_in[6];
    const float* w    = (const float*)d_in[7];
    const float* bias = (const float*)d_in[8];
    float* out = (float*)d_out;

    // 81920 warps, 8 warps/block -> 10240 blocks, 5 blocks per (b,n)
    fused_logits_kernel<<<(B_ * N_ * T_) / WARPS_PER_BLOCK, 32 * WARPS_PER_BLOCK>>>(
        poly, idx, pts, z, df, ctx, fa, w, bias, out);
}

// round 13
// speedup vs baseline: 2.3361x; 2.3361x over previous
#include <cuda_runtime.h>
#include <cstdint>

// Problem shape constants (fixed by setup_inputs)
#define B_ 32
#define M_ 512
#define L_ 128
#define N_ 64
#define T_ 40
#define A_ 6
#define Z_ 64
#define C_ 3

#define WARPS_PER_BLOCK 8

// ---------------------------------------------------------------------------
// Key algebraic fact: the frenet projection contributes a per-(b,n) constant
// (frenet·u_ctx_w + u_ctx_b) to u, uniform across actions. The reference then
// subtracts the feasibility-masked mean over actions; the masked mean of a
// constant IS the constant (denominator = faf.sum >= 1), so the projection
// cancels from the logits exactly. Residual fp-rounding difference vs the
// reference is ~1e-7 relative — far under the 1e-3 gate (and matches the
// rel_err all previous passing rounds measured anyway).
//
// Therefore: pure streaming kernel. One warp per (b,n,t).
//   logits[a] = <df[a,:], z> + (ctx[a,:]·w − masked_mean_a(ctx·w))
//
// Layout: lanes split into two 16-lane halves; half h handles actions
// {h, 2+h, 4+h}. z held as float4 over 16 lanes (replicated per half);
// df read as 3x coalesced 512B LDG.128 (pair p = actions 2p,2p+1);
// reductions are 4-level butterflies within each half (12 SHFLs total).
// ---------------------------------------------------------------------------
__global__ __launch_bounds__(32 * WARPS_PER_BLOCK)
void logits_kernel(const float* __restrict__ df,
                   const float* __restrict__ ctx,
                   const int* __restrict__ fa,
                   const float* __restrict__ z,
                   const float* __restrict__ w,
                   float* __restrict__ out) {
    const int gw   = (blockIdx.x * blockDim.x + threadIdx.x) >> 5;  // (b*N+n)*T+t
    const int lane = threadIdx.x & 31;
    if (gw >= B_ * N_ * T_) return;
    const int bn = gw / T_;

    const int h = lane >> 4;      // half: 0 -> even actions, 1 -> odd actions
    const int q = lane & 15;

    // z as float4 per lane, replicated across halves (L1/L2-resident)
    const float4 z4 = *reinterpret_cast<const float4*>(z + (size_t)bn * Z_ + 4 * q);

    // 3 coalesced 512B loads: pair p covers actions (2p, 2p+1).
    // Issued back-to-back before any consumption -> MLP = 3 big loads/warp.
    const float* dfb = df + (size_t)gw * (A_ * Z_) + 4 * lane;
    float4 v[3];
#pragma unroll
    for (int p = 0; p < 3; ++p)
        v[p] = *reinterpret_cast<const float4*>(dfb + p * 2 * Z_);

    // ctx: 18 contiguous floats, lanes 0..17 coalesced; fa: 6 ints
    const size_t cb = (size_t)gw * (A_ * C_);
    const float cv = (lane < A_ * C_) ? __ldg(ctx + cb + lane) : 0.f;
    const int f    = (lane < A_) ? __ldg(fa + (size_t)gw * A_ + lane) : 0;

    float acc[3];
#pragma unroll
    for (int p = 0; p < 3; ++p)
        acc[p] = v[p].x * z4.x + v[p].y * z4.y + v[p].z * z4.z + v[p].w * z4.w;

    // 4-level butterfly within each 16-lane half:
    // afterwards every lane in half h holds the full dot for action 2p+h
#pragma unroll
    for (int p = 0; p < 3; ++p) {
#pragma unroll
        for (int off = 8; off > 0; off >>= 1)
            acc[p] += __shfl_xor_sync(0xffffffffu, acc[p], off);
    }

    // ctx·w per action: segmented 3-sum, valid at lanes 3a (a = 0..5)
    const float w0 = __ldg(w), w1 = __ldg(w + 1), w2 = __ldg(w + 2);
    const int   c  = lane % 3;
    const float wc = (c == 0) ? w0 : ((c == 1) ? w1 : w2);
    const float pterm = cv * wc;
    const float qs = pterm + __shfl_down_sync(0xffffffffu, pterm, 1)
                           + __shfl_down_sync(0xffffffffu, pterm, 2);
    // lane in half h picks up ctx-part of u for its actions 2r+h (r = 0..2)
    float ua[3];
#pragma unroll
    for (int r = 0; r < 3; ++r)
        ua[r] = __shfl_sync(0xffffffffu, qs, 3 * (2 * r + h));

    // feasibility mask (fallback: all feasible) + masked mean of ctx-part
    const unsigned fm = __ballot_sync(0xffffffffu, (f != 0) && (lane < A_));
    const unsigned em = fm ? fm : 0x3fu;
    const int cnt = __popc(em);
    float part = 0.f;
#pragma unroll
    for (int r = 0; r < 3; ++r)
        part += ((em >> (2 * r + h)) & 1u) ? ua[r] : 0.f;
    // each half's `part` is uniform across its lanes; cross-half add = total
    const float tot  = part + __shfl_xor_sync(0xffffffffu, part, 16);
    const float mean = tot / fmaxf((float)cnt, 1e-6f);

    // lanes 0 and 16 write even/odd actions respectively
    if (q == 0) {
        float* ob = out + (size_t)gw * A_ + h;
#pragma unroll
        for (int r = 0; r < 3; ++r)
            ob[2 * r] = acc[r] + (ua[r] - mean);
    }
}

// ---------------------------------------------------------------------------
// kernel_launch: inputs in metadata order:
//   0 map_polylines (B,M,L,2) f32   1 idx (B,N) i32       2 pts (B,N,2) f32
//   3 z (B,N,Z) f32                 4 decision_features (B,N,T,A,Z) f32
//   5 ctx_features (B,N,T,A,C) f32  6 feasible_actions (B,N,T,A) i32
//   7 u_ctx_w (C,) f32              8 u_ctx_b (1,) f32
// output: logits (B,N,T,A) f32
// Inputs 0,1,2,8 are provably unused in the output (projection term cancels
// under the masked mean; bias likewise).
// ---------------------------------------------------------------------------
extern "C" void kernel_launch(void* const* d_in, const int* in_sizes, int n_in,
                              void* d_out, int out_size) {
    const float* z    = (const float*)d_in[3];
    const float* df   = (const float*)d_in[4];
    const float* ctx  = (const float*)d_in[5];
    const int*   fa   = (const int*)  d_in[6];
    const float* w    = (const float*)d_in[7];
    float* out = (float*)d_out;

    // 81920 warps, 8 warps/block -> 10240 blocks
    logits_kernel<<<(B_ * N_ * T_) / WARPS_PER_BLOCK, 32 * WARPS_PER_BLOCK>>>(
        df, ctx, fa, z, w, out);
}

// round 15
// speedup vs baseline: 2.4402x; 1.0446x over previous
#include <cuda_runtime.h>
#include <cstdint>

// Problem shape constants (fixed by setup_inputs)
#define B_ 32
#define M_ 512
#define L_ 128
#define N_ 64
#define T_ 40
#define A_ 6
#define Z_ 64
#define C_ 3

#define WARPS_PER_BLOCK 8
#define TP_ (T_ / 2)   // t-pairs per (b,n) = 20

// ---------------------------------------------------------------------------
// Algebraic fact (validated R13, rel_err 1.05e-7): the frenet projection term
// (frenet·u_ctx_w + u_ctx_b) is uniform across actions, and the reference's
// feasibility-masked mean subtraction removes any per-(b,n) constant exactly
// (masked mean of a constant is the constant; denominator = faf.sum >= 1).
// So logits[a] = <df[a,:], z> + (ctx[a,:]·w − masked_mean_a(ctx·w)) and the
// entire polyline projection pipeline is dead code.
//
// This round: TWO t's per warp. df rows for consecutive t's of one (b,n) are
// contiguous (384 floats each), so the warp issues 6 back-to-back coalesced
// 512B LDG.128 spanning 3072 contiguous bytes before any consumption —
// double the bytes in flight per scheduler slot vs R13 (issue=40% showed
// warps were starving in long_scoreboard after only 3 loads).
//
// Lane layout: halves h=0/1 own even/odd actions; z as float4 over 16 lanes,
// replicated per half. acc[p] p=0..2 -> t0 actions 2p+h, p=3..5 -> t1.
// ---------------------------------------------------------------------------
__global__ __launch_bounds__(32 * WARPS_PER_BLOCK)
void logits_kernel(const float* __restrict__ df,
                   const float* __restrict__ ctx,
                   const int* __restrict__ fa,
                   const float* __restrict__ z,
                   const float* __restrict__ w,
                   float* __restrict__ out) {
    const int gwp  = (blockIdx.x * blockDim.x + threadIdx.x) >> 5;  // warp id
    const int lane = threadIdx.x & 31;
    if (gwp >= B_ * N_ * TP_) return;
    const int bn  = gwp / TP_;
    const int gw0 = bn * T_ + 2 * (gwp % TP_);   // first of two consecutive t's

    const int h = lane >> 4;      // half: 0 -> even actions, 1 -> odd actions
    const int q = lane & 15;

    // z as float4 per lane, replicated across halves (L1/L2-resident)
    const float4 z4 = *reinterpret_cast<const float4*>(z + (size_t)bn * Z_ + 4 * q);

    // 6 coalesced 512B loads covering df rows for t0 and t1 (3072B contiguous).
    // p = 0..2 -> t0 action-pairs, p = 3..5 -> t1 action-pairs.
    const float* dfb = df + (size_t)gw0 * (A_ * Z_) + 4 * lane;
    float4 v[6];
#pragma unroll
    for (int p = 0; p < 6; ++p)
        v[p] = *reinterpret_cast<const float4*>(dfb + p * 2 * Z_);

    // ctx: 36 contiguous floats (18 per t); fa: 12 contiguous ints
    const size_t cb = (size_t)gw0 * (A_ * C_);
    const float cv0 = (lane < A_ * C_) ? __ldg(ctx + cb + lane) : 0.f;
    const float cv1 = (lane < A_ * C_) ? __ldg(ctx + cb + A_ * C_ + lane) : 0.f;
    const int f = (lane < 2 * A_) ? __ldg(fa + (size_t)gw0 * A_ + lane) : 0;

    float acc[6];
#pragma unroll
    for (int p = 0; p < 6; ++p)
        acc[p] = v[p].x * z4.x + v[p].y * z4.y + v[p].z * z4.z + v[p].w * z4.w;

    // 4-level butterfly within each 16-lane half
#pragma unroll
    for (int p = 0; p < 6; ++p) {
#pragma unroll
        for (int off = 8; off > 0; off >>= 1)
            acc[p] += __shfl_xor_sync(0xffffffffu, acc[p], off);
    }

    // ctx·w per action for both t's: segmented 3-sums, valid at lanes 3a
    const float w0 = __ldg(w), w1 = __ldg(w + 1), w2 = __ldg(w + 2);
    const int   c  = lane % 3;
    const float wc = (c == 0) ? w0 : ((c == 1) ? w1 : w2);
    const float pt0 = cv0 * wc;
    const float pt1 = cv1 * wc;
    const float qs0 = pt0 + __shfl_down_sync(0xffffffffu, pt0, 1)
                          + __shfl_down_sync(0xffffffffu, pt0, 2);
    const float qs1 = pt1 + __shfl_down_sync(0xffffffffu, pt1, 1)
                          + __shfl_down_sync(0xffffffffu, pt1, 2);
    float ua0[3], ua1[3];
#pragma unroll
    for (int r = 0; r < 3; ++r) {
        const int src = 3 * (2 * r + h);
        ua0[r] = __shfl_sync(0xffffffffu, qs0, src);
        ua1[r] = __shfl_sync(0xffffffffu, qs1, src);
    }

    // One ballot serves both t's: lanes 0..5 -> t0 mask, lanes 6..11 -> t1
    const unsigned bal = __ballot_sync(0xffffffffu, (f != 0) && (lane < 2 * A_));
    unsigned em0 = bal & 0x3fu;         if (!em0) em0 = 0x3fu;
    unsigned em1 = (bal >> A_) & 0x3fu; if (!em1) em1 = 0x3fu;
    const int cnt0 = __popc(em0), cnt1 = __popc(em1);

    float part0 = 0.f, part1 = 0.f;
#pragma unroll
    for (int r = 0; r < 3; ++r) {
        const int a = 2 * r + h;
        part0 += ((em0 >> a) & 1u) ? ua0[r] : 0.f;
        part1 += ((em1 >> a) & 1u) ? ua1[r] : 0.f;
    }
    // each half's part is uniform across its lanes; cross-half add = total
    const float tot0  = part0 + __shfl_xor_sync(0xffffffffu, part0, 16);
    const float tot1  = part1 + __shfl_xor_sync(0xffffffffu, part1, 16);
    const float mean0 = tot0 / fmaxf((float)cnt0, 1e-6f);
    const float mean1 = tot1 / fmaxf((float)cnt1, 1e-6f);

    // lanes 0 and 16 write even/odd actions for both t's (12 contiguous floats)
    if (q == 0) {
        float* ob = out + (size_t)gw0 * A_ + h;
#pragma unroll
        for (int r = 0; r < 3; ++r) {
            ob[2 * r]      = acc[r]     + (ua0[r] - mean0);
            ob[A_ + 2 * r] = acc[3 + r] + (ua1[r] - mean1);
        }
    }
}

// ---------------------------------------------------------------------------
// kernel_launch: inputs in metadata order:
//   0 map_polylines (B,M,L,2) f32   1 idx (B,N) i32       2 pts (B,N,2) f32
//   3 z (B,N,Z) f32                 4 decision_features (B,N,T,A,Z) f32
//   5 ctx_features (B,N,T,A,C) f32  6 feasible_actions (B,N,T,A) i32
//   7 u_ctx_w (C,) f32              8 u_ctx_b (1,) f32
// output: logits (B,N,T,A) f32
// Inputs 0,1,2,8 provably do not affect the output (constant term cancels
// under the masked mean).
// ---------------------------------------------------------------------------
extern "C" void kernel_launch(void* const* d_in, const int* in_sizes, int n_in,
                              void* d_out, int out_size) {
    const float* z    = (const float*)d_in[3];
    const float* df   = (const float*)d_in[4];
    const float* ctx  = (const float*)d_in[5];
    const int*   fa   = (const int*)  d_in[6];
    const float* w    = (const float*)d_in[7];
    float* out = (float*)d_out;

    // 40960 pair-warps, 8 warps/block -> 5120 blocks
    logits_kernel<<<(B_ * N_ * TP_) / WARPS_PER_BLOCK, 32 * WARPS_PER_BLOCK>>>(
        df, ctx, fa, z, w, out);
}

// round 16
// speedup vs baseline: 2.4643x; 1.0099x over previous
#include <cuda_runtime.h>
#include <cstdint>

// Problem shape constants (fixed by setup_inputs)
#define B_ 32
#define M_ 512
#define L_ 128
#define N_ 64
#define T_ 40
#define A_ 6
#define Z_ 64
#define C_ 3

#define WARPS_PER_BLOCK 8
#define KITER 5                 // t's per warp (40 = 8 groups * 5)
#define GROUPS (T_ / KITER)     // 8 warp-groups per (b,n)

// ---------------------------------------------------------------------------
// Algebraic fact (validated since R13, rel_err 1.05e-7): the frenet projection
// term is uniform across actions and cancels exactly under the reference's
// feasibility-masked mean subtraction. So
//   logits[a] = <df[a,:], z> + (ctx[a,:]·w − masked_mean_a(ctx·w))
// and the polyline projection pipeline is dead code.
//
// R16: software-pipelined t-loop. One warp owns 5 consecutive t's of one
// (b,n); loads for iteration j+1 (3x coalesced 512B LDG.128 + ctx + fa) are
// issued BEFORE the compute of iteration j, so every warp keeps ~1.6KB in
// flight even during its shuffle chains. This converts the bursty
// load→stall→compute duty cycle (R13/R15: DRAM pinned at 62%) into a steady
// request stream.
//
// Per-t body is R13's validated layout: halves h=0/1 own even/odd actions,
// z as float4 over 16 lanes (replicated per half), 4-level butterflies.
// ---------------------------------------------------------------------------
__global__ __launch_bounds__(32 * WARPS_PER_BLOCK)
void logits_kernel(const float* __restrict__ df,
                   const float* __restrict__ ctx,
                   const int* __restrict__ fa,
                   const float* __restrict__ z,
                   const float* __restrict__ w,
                   float* __restrict__ out) {
    const int wi   = (blockIdx.x * blockDim.x + threadIdx.x) >> 5;
    const int lane = threadIdx.x & 31;
    if (wi >= B_ * N_ * GROUPS) return;
    const int bn  = wi / GROUPS;
    const int gw0 = bn * T_ + (wi % GROUPS) * KITER;  // first t of this warp

    const int h = lane >> 4;      // half: 0 -> even actions, 1 -> odd actions
    const int q = lane & 15;

    // z as float4 per lane, replicated across halves (L2-resident)
    const float4 z4 = *reinterpret_cast<const float4*>(z + (size_t)bn * Z_ + 4 * q);

    const float w0 = __ldg(w), w1 = __ldg(w + 1), w2 = __ldg(w + 2);
    const int   c  = lane % 3;
    const float wc = (c == 0) ? w0 : ((c == 1) ? w1 : w2);

    // ---- prologue: loads for iteration 0 ----
    const float* dfb0 = df + (size_t)gw0 * (A_ * Z_) + 4 * lane;
    float4 v[3];
#pragma unroll
    for (int p = 0; p < 3; ++p)
        v[p] = *reinterpret_cast<const float4*>(dfb0 + p * 2 * Z_);
    float cv = (lane < A_ * C_)
                   ? __ldg(ctx + (size_t)gw0 * (A_ * C_) + lane) : 0.f;
    int f = (lane < A_) ? __ldg(fa + (size_t)gw0 * A_ + lane) : 0;

#pragma unroll
    for (int j = 0; j < KITER; ++j) {
        const int gw = gw0 + j;

        // ---- prefetch iteration j+1 (in flight during compute below) ----
        float4 nv[3];
        float  ncv = 0.f;
        int    nf  = 0;
        if (j + 1 < KITER) {
            const float* dfb = df + (size_t)(gw + 1) * (A_ * Z_) + 4 * lane;
#pragma unroll
            for (int p = 0; p < 3; ++p)
                nv[p] = *reinterpret_cast<const float4*>(dfb + p * 2 * Z_);
            if (lane < A_ * C_)
                ncv = __ldg(ctx + (size_t)(gw + 1) * (A_ * C_) + lane);
            if (lane < A_)
                nf = __ldg(fa + (size_t)(gw + 1) * A_ + lane);
        }

        // ---- compute iteration j (R13 body) ----
        float acc[3];
#pragma unroll
        for (int p = 0; p < 3; ++p)
            acc[p] = v[p].x * z4.x + v[p].y * z4.y + v[p].z * z4.z + v[p].w * z4.w;

        // 4-level butterfly within each 16-lane half:
        // afterwards every lane in half h holds the full dot for action 2p+h
#pragma unroll
        for (int p = 0; p < 3; ++p) {
#pragma unroll
            for (int off = 8; off > 0; off >>= 1)
                acc[p] += __shfl_xor_sync(0xffffffffu, acc[p], off);
        }

        // ctx·w per action: segmented 3-sum, valid at lanes 3a (a = 0..5)
        const float pterm = cv * wc;
        const float qs = pterm + __shfl_down_sync(0xffffffffu, pterm, 1)
                               + __shfl_down_sync(0xffffffffu, pterm, 2);
        float ua[3];
#pragma unroll
        for (int r = 0; r < 3; ++r)
            ua[r] = __shfl_sync(0xffffffffu, qs, 3 * (2 * r + h));

        // feasibility mask (fallback: all feasible) + masked mean of ctx-part
        const unsigned fm = __ballot_sync(0xffffffffu, (f != 0) && (lane < A_));
        const unsigned em = fm ? fm : 0x3fu;
        const int cnt = __popc(em);
        float part = 0.f;
#pragma unroll
        for (int r = 0; r < 3; ++r)
            part += ((em >> (2 * r + h)) & 1u) ? ua[r] : 0.f;
        const float tot  = part + __shfl_xor_sync(0xffffffffu, part, 16);
        const float mean = tot / fmaxf((float)cnt, 1e-6f);

        // lanes 0 and 16 write even/odd actions respectively
        if (q == 0) {
            float* ob = out + (size_t)gw * A_ + h;
#pragma unroll
            for (int r = 0; r < 3; ++r)
                ob[2 * r] = acc[r] + (ua[r] - mean);
        }

        // ---- rotate buffers ----
        if (j + 1 < KITER) {
#pragma unroll
            for (int p = 0; p < 3; ++p) v[p] = nv[p];
            cv = ncv;
            f  = nf;
        }
    }
}

// ---------------------------------------------------------------------------
// kernel_launch: inputs in metadata order:
//   0 map_polylines (B,M,L,2) f32   1 idx (B,N) i32       2 pts (B,N,2) f32
//   3 z (B,N,Z) f32                 4 decision_features (B,N,T,A,Z) f32
//   5 ctx_features (B,N,T,A,C) f32  6 feasible_actions (B,N,T,A) i32
//   7 u_ctx_w (C,) f32              8 u_ctx_b (1,) f32
// output: logits (B,N,T,A) f32
// Inputs 0,1,2,8 provably do not affect the output (constant term cancels
// under the masked mean).
// ---------------------------------------------------------------------------
extern "C" void kernel_launch(void* const* d_in, const int* in_sizes, int n_in,
                              void* d_out, int out_size) {
    const float* z    = (const float*)d_in[3];
    const float* df   = (const float*)d_in[4];
    const float* ctx  = (const float*)d_in[5];
    const int*   fa   = (const int*)  d_in[6];
    const float* w    = (const float*)d_in[7];
    float* out = (float*)d_out;

    // 16384 warps (5 t's each), 8 warps/block -> 2048 blocks
    logits_kernel<<<(B_ * N_ * GROUPS) / WARPS_PER_BLOCK, 32 * WARPS_PER_BLOCK>>>(
        df, ctx, fa, z, w, out);
}